// round 3
// baseline (speedup 1.0000x reference)
#include <cuda_runtime.h>
#include <math.h>

#define NFFT 512
#define HOP  128
#define LSIG 160000
#define BB   16
#define CC   4
#define TT   1251
#define FDIM 257
#define KFEAT (4 * CC * FDIM)   // 4112
#define CF   (CC * FDIM)        // 1028

#define PI_D 3.14159265358979323846

struct c2 { float x, y; };

__device__ __forceinline__ c2 cmul(c2 a, c2 b){ c2 r; r.x = a.x*b.x - a.y*b.y; r.y = a.x*b.y + a.y*b.x; return r; }
__device__ __forceinline__ c2 cadd(c2 a, c2 b){ c2 r; r.x = a.x+b.x; r.y = a.y+b.y; return r; }
__device__ __forceinline__ c2 csub(c2 a, c2 b){ c2 r; r.x = a.x-b.x; r.y = a.y-b.y; return r; }
__device__ __forceinline__ c2 mulnegi(c2 a){ c2 r; r.x = a.y; r.y = -a.x; return r; }

// radix-8 DFT: o[k] = sum_j v[j] * w8^{j*k}, w8 = exp(-2*pi*i/8)
__device__ __forceinline__ void radix8(const c2* v, c2* o) {
    const float S = 0.70710678118654752f;
    c2 a0=cadd(v[0],v[4]), a1=csub(v[0],v[4]);
    c2 a2=cadd(v[2],v[6]), a3=csub(v[2],v[6]);
    c2 b0=cadd(v[1],v[5]), b1=csub(v[1],v[5]);
    c2 b2=cadd(v[3],v[7]), b3=csub(v[3],v[7]);
    c2 ia3 = mulnegi(a3), ib3 = mulnegi(b3);
    c2 c0=cadd(a0,a2), c1=csub(a0,a2);
    c2 e2=cadd(a1,ia3), e3=csub(a1,ia3);
    c2 d0=cadd(b0,b2), d1=csub(b0,b2);
    c2 d2=cadd(b1,ib3), d3=csub(b1,ib3);
    c2 w1d2; w1d2.x = S*(d2.x + d2.y); w1d2.y = S*(d2.y - d2.x);
    c2 w3d3; w3d3.x = S*(d3.y - d3.x); w3d3.y = -S*(d3.x + d3.y);
    c2 id1 = mulnegi(d1);
    o[0]=cadd(c0,d0);    o[4]=csub(c0,d0);
    o[2]=cadd(c1,id1);   o[6]=csub(c1,id1);
    o[1]=cadd(e2,w1d2);  o[5]=csub(e2,w1d2);
    o[3]=cadd(e3,w3d3);  o[7]=csub(e3,w3d3);
}

__device__ __align__(16) float g_sv[2 * CF];   // [0..CF)=cos/2, [CF..2CF)=sin/2
__device__ float g_dt[CC];                      // tdoa[c] - tdoa[0]

// ---------------------------------------------------------------------------
// prepA: TDOA (tiny, 1 warp, accurate trig for reference fidelity)
// ---------------------------------------------------------------------------
__global__ void prepA_kernel(const float* __restrict__ angle,
                             const float* __restrict__ mic_pos) {
    __shared__ float tdoa[CC];
    int tid = threadIdx.x;
    if (tid < CC) {
        const float half_pi = (float)(PI_D / 2.0);
        float sin90 = sinf(half_pi);
        float cos90 = cosf(half_pi);
        float sum = 0.f;
        for (int b = 0; b < BB; b++) {
            float rad = -angle[b] * (float)(PI_D / 180.0);
            float lx = cosf(rad) * sin90;
            float ly = sinf(rad) * sin90;
            float lz = cos90;
            const float* mp = mic_pos + (b * CC + tid) * 3;
            float dx = mp[0] - lx, dy = mp[1] - ly, dz = mp[2] - lz;
            sum += dx * dx + dy * dy + dz * dz;
        }
        tdoa[tid] = sqrtf(sum);
    }
    __syncwarp();
    if (tid < CC) g_dt[tid] = tdoa[tid] - tdoa[0];
}

// ---------------------------------------------------------------------------
// prepB: steering-vector table (parallel, accurate sincosf)
// ---------------------------------------------------------------------------
__global__ void prepB_kernel() {
    int i = blockIdx.x * 256 + threadIdx.x;
    if (i >= CF) return;
    int c = i / FDIM;
    int f = i - c * FDIM;
    const float coef = (float)(-2.0 * PI_D * 16000.0 / (512.0 * 340.4));
    float ph = coef * (float)f * g_dt[c];
    float s, co;
    sincosf(ph, &s, &co);
    g_sv[i]      = co * 0.5f;   // / ||sv|| (= sqrt(C) = 2)
    g_sv[CF + i] = s * 0.5f;
}

// ---------------------------------------------------------------------------
// STFT: 256-thr block = 4 FFT units (64 thr). Each unit: one packed complex
// FFT (two real channels, one frame) via 3 radix-8 register passes.
// Twiddles computed in registers (__sincosf base + iterated cmul).
// Writes X.re/X.im feature groups with float4 stores.
// ---------------------------------------------------------------------------
__global__ void __launch_bounds__(256) stft_kernel(const float* __restrict__ x,
                                                   float* __restrict__ out) {
    __shared__ c2 skew[4][520];   // 8 rows of 65 (64 + pad)
    __shared__ c2 nat[4][512];    // natural-order result

    const int tid = threadIdx.x;
    const int u   = tid >> 6;
    const int tau = tid & 63;
    const int t   = blockIdx.x * 4 + u;
    const int by  = blockIdx.y;
    const int b   = by >> 1;
    const int pr  = by & 1;              // channel pair (2pr, 2pr+1)
    const bool active = (t < TT);

    c2 v[8], o8[8];

    // ---- pass 1: windowed load, radix-8 over n2, twiddle W64^{n1*k0} ----
    if (active) {
        const float c8[8] = {1.f, 0.70710678f, 0.f, -0.70710678f, -1.f, -0.70710678f, 0.f, 0.70710678f};
        const float s8[8] = {0.f, 0.70710678f, 1.f, 0.70710678f, 0.f, -0.70710678f, -1.f, -0.70710678f};
        float sth, cth;
        __sincosf((float)(2.0 * PI_D / 512.0) * (float)tau, &sth, &cth);

        const float* xa = x + (size_t)(b * CC + 2 * pr) * LSIG;
        const float* xb = xa + LSIG;
#pragma unroll
        for (int n2 = 0; n2 < 8; n2++) {
            int n = n2 * 64 + tau;
            int p = t * HOP + n - 256;                       // reflect pad
            int s = (p < 0) ? -p : ((p >= LSIG) ? 2 * LSIG - 2 - p : p);
            float cosn = c8[n2] * cth - s8[n2] * sth;        // cos(2*pi*n/512)
            float w = 0.5f - 0.5f * cosn;
            v[n2].x = xa[s] * w;
            v[n2].y = xb[s] * w;
        }
        radix8(v, o8);
        int n1 = tau >> 3;
        float sb, cb;
        __sincosf((float)(-2.0 * PI_D / 64.0) * (float)n1, &sb, &cb);
        c2 wbase; wbase.x = cb; wbase.y = sb;
        c2 w; w.x = 1.f; w.y = 0.f;
#pragma unroll
        for (int k0 = 0; k0 < 8; k0++) {
            skew[u][k0 * 65 + tau] = cmul(o8[k0], w);
            w = cmul(w, wbase);
        }
    }
    __syncthreads();

    // ---- pass 2: radix-8 over n1, twiddle W512^{n0*k0} * W64^{n0*k1} ----
    if (active) {
        int k0 = tau >> 3, n0 = tau & 7;
#pragma unroll
        for (int n1 = 0; n1 < 8; n1++) v[n1] = skew[u][k0 * 65 + n1 * 8 + n0];
        radix8(v, o8);
        float s0, c0, ss, cs;
        __sincosf((float)(-2.0 * PI_D / 512.0) * (float)(n0 * k0), &s0, &c0);
        __sincosf((float)(-2.0 * PI_D / 64.0) * (float)n0, &ss, &cs);
        c2 w; w.x = c0; w.y = s0;
        c2 step; step.x = cs; step.y = ss;
#pragma unroll
        for (int k1 = 0; k1 < 8; k1++) {
            skew[u][k0 * 65 + k1 * 8 + n0] = cmul(o8[k1], w);
            w = cmul(w, step);
        }
    }
    __syncthreads();

    // ---- pass 3: radix-8 over n0 -> nat[64*k2 + 8*k1 + k0] ----
    if (active) {
        int k0 = tau >> 3, k1 = tau & 7;
#pragma unroll
        for (int n0 = 0; n0 < 8; n0++) v[n0] = skew[u][k0 * 65 + k1 * 8 + n0];
        radix8(v, o8);
#pragma unroll
        for (int k2 = 0; k2 < 8; k2++) nat[u][k2 * 64 + k1 * 8 + k0] = o8[k2];
    }
    __syncthreads();

    // ---- unpack + vectorized store of X.re / X.im ----
    if (active) {
        float* row = out + ((size_t)b * TT + t) * KFEAT;
        const int ch   = tau >> 5;        // 0 -> channel 2pr, 1 -> 2pr+1
        const int lane = tau & 31;
        const int c    = 2 * pr + ch;
        const int h    = (4 - c) & 3;     // scalar head so quads are 16B-aligned
        const int nq   = (FDIM - h) >> 2; // full quads
        float* reB = row + c * FDIM;
        float* imB = reB + CF;

#pragma unroll
        for (int it = 0; it < 2; it++) {
            int j = lane + it * 32;
            if (j < nq) {
                int k = h + 4 * j;
                c2 zk0 = nat[u][k],     zk1 = nat[u][k + 1];
                c2 zk2 = nat[u][k + 2], zk3 = nat[u][k + 3];
                c2 zm0 = nat[u][(512 - k) & 511];
                c2 zm1 = nat[u][511 - k];
                c2 zm2 = nat[u][510 - k];
                c2 zm3 = nat[u][509 - k];
                float4 re, im;
                if (ch == 0) {   // A = even channel
                    re.x = 0.5f*(zk0.x + zm0.x); im.x = 0.5f*(zk0.y - zm0.y);
                    re.y = 0.5f*(zk1.x + zm1.x); im.y = 0.5f*(zk1.y - zm1.y);
                    re.z = 0.5f*(zk2.x + zm2.x); im.z = 0.5f*(zk2.y - zm2.y);
                    re.w = 0.5f*(zk3.x + zm3.x); im.w = 0.5f*(zk3.y - zm3.y);
                } else {         // B = odd channel
                    re.x = 0.5f*(zk0.y + zm0.y); im.x = 0.5f*(zm0.x - zk0.x);
                    re.y = 0.5f*(zk1.y + zm1.y); im.y = 0.5f*(zm1.x - zk1.x);
                    re.z = 0.5f*(zk2.y + zm2.y); im.z = 0.5f*(zm2.x - zk2.x);
                    re.w = 0.5f*(zk3.y + zm3.y); im.w = 0.5f*(zm3.x - zk3.x);
                }
                *reinterpret_cast<float4*>(reB + k) = re;
                *reinterpret_cast<float4*>(imB + k) = im;
            }
        }
        if (lane == 0) {          // head (k < h) + tail (k >= h + 4*nq) scalars
            for (int k = 0; k < h; k++) {
                c2 zk = nat[u][k], zm = nat[u][(512 - k) & 511];
                if (ch == 0) { reB[k] = 0.5f*(zk.x + zm.x); imB[k] = 0.5f*(zk.y - zm.y); }
                else         { reB[k] = 0.5f*(zk.y + zm.y); imB[k] = 0.5f*(zm.x - zk.x); }
            }
            for (int k = h + 4 * nq; k < FDIM; k++) {
                c2 zk = nat[u][k], zm = nat[u][(512 - k) & 511];
                if (ch == 0) { reB[k] = 0.5f*(zk.x + zm.x); imB[k] = 0.5f*(zk.y - zm.y); }
                else         { reB[k] = 0.5f*(zk.y + zm.y); imB[k] = 0.5f*(zm.x - zk.x); }
            }
        }
    }
}

// ---------------------------------------------------------------------------
// SV broadcast: groups 2 & 3, constant over t. Pure float4 streaming.
// ---------------------------------------------------------------------------
__global__ void __launch_bounds__(256) sv_kernel(float* __restrict__ out) {
    const float4* s4 = reinterpret_cast<const float4*>(g_sv);
    float4* o4 = reinterpret_cast<float4*>(out + (size_t)blockIdx.x * KFEAT + 2 * CF);
    for (int i = threadIdx.x; i < (2 * CF) / 4; i += 256) o4[i] = s4[i];
}

// ---------------------------------------------------------------------------
extern "C" void kernel_launch(void* const* d_in, const int* in_sizes, int n_in,
                              void* d_out, int out_size) {
    const float* x     = (const float*)d_in[0];
    const float* angle = (const float*)d_in[1];
    const float* mic   = (const float*)d_in[2];
    float* out = (float*)d_out;

    prepA_kernel<<<1, 32>>>(angle, mic);
    prepB_kernel<<<(CF + 255) / 256, 256>>>();

    dim3 grid((TT + 3) / 4, BB * 2);
    stft_kernel<<<grid, 256>>>(x, out);

    sv_kernel<<<BB * TT, 256>>>(out);
}

// round 4
// speedup vs baseline: 1.1498x; 1.1498x over previous
#include <cuda_runtime.h>
#include <math.h>

#define NFFT 512
#define HOP  128
#define LSIG 160000
#define BB   16
#define CC   4
#define TT   1251
#define FDIM 257
#define KFEAT (4 * CC * FDIM)   // 4112
#define CF   (CC * FDIM)        // 1028

#define PI_D 3.14159265358979323846

struct c2 { float x, y; };

__device__ __forceinline__ c2 cmul(c2 a, c2 b){ c2 r; r.x = a.x*b.x - a.y*b.y; r.y = a.x*b.y + a.y*b.x; return r; }
__device__ __forceinline__ c2 cadd(c2 a, c2 b){ c2 r; r.x = a.x+b.x; r.y = a.y+b.y; return r; }
__device__ __forceinline__ c2 csub(c2 a, c2 b){ c2 r; r.x = a.x-b.x; r.y = a.y-b.y; return r; }
__device__ __forceinline__ c2 mulnegi(c2 a){ c2 r; r.x = a.y; r.y = -a.x; return r; }

// radix-8 DFT: o[k] = sum_j v[j] * w8^{j*k}, w8 = exp(-2*pi*i/8)
__device__ __forceinline__ void radix8(const c2* v, c2* o) {
    const float S = 0.70710678118654752f;
    c2 a0=cadd(v[0],v[4]), a1=csub(v[0],v[4]);
    c2 a2=cadd(v[2],v[6]), a3=csub(v[2],v[6]);
    c2 b0=cadd(v[1],v[5]), b1=csub(v[1],v[5]);
    c2 b2=cadd(v[3],v[7]), b3=csub(v[3],v[7]);
    c2 ia3 = mulnegi(a3), ib3 = mulnegi(b3);
    c2 c0=cadd(a0,a2), c1=csub(a0,a2);
    c2 e2=cadd(a1,ia3), e3=csub(a1,ia3);
    c2 d0=cadd(b0,b2), d1=csub(b0,b2);
    c2 d2=cadd(b1,ib3), d3=csub(b1,ib3);
    c2 w1d2; w1d2.x = S*(d2.x + d2.y); w1d2.y = S*(d2.y - d2.x);
    c2 w3d3; w3d3.x = S*(d3.y - d3.x); w3d3.y = -S*(d3.x + d3.y);
    c2 id1 = mulnegi(d1);
    o[0]=cadd(c0,d0);    o[4]=csub(c0,d0);
    o[2]=cadd(c1,id1);   o[6]=csub(c1,id1);
    o[1]=cadd(e2,w1d2);  o[5]=csub(e2,w1d2);
    o[3]=cadd(e3,w3d3);  o[7]=csub(e3,w3d3);
}

__device__ __align__(16) float g_sv[2 * CF];   // [0..CF)=cos/2, [CF..2CF)=sin/2

// ---------------------------------------------------------------------------
// Prep: TDOA + steering-vector table (single block, 1024 threads)
// ---------------------------------------------------------------------------
__global__ void __launch_bounds__(1024) prep_kernel(const float* __restrict__ angle,
                                                    const float* __restrict__ mic_pos) {
    __shared__ float tdoa[CC];
    int tid = threadIdx.x;
    if (tid < CC) {
        const float half_pi = (float)(PI_D / 2.0);
        float sin90 = sinf(half_pi);   // fp32 quirks reproduced
        float cos90 = cosf(half_pi);
        float sum = 0.f;
        for (int b = 0; b < BB; b++) {
            float rad = -angle[b] * (float)(PI_D / 180.0);
            float lx = cosf(rad) * sin90;
            float ly = sinf(rad) * sin90;
            float lz = cos90;          // DIST = 1.0
            const float* mp = mic_pos + (b * CC + tid) * 3;
            float dx = mp[0] - lx, dy = mp[1] - ly, dz = mp[2] - lz;
            sum += dx * dx + dy * dy + dz * dz;
        }
        tdoa[tid] = sqrtf(sum);
    }
    __syncthreads();
    const float d0 = tdoa[0];
    const float coef = (float)(-2.0 * PI_D * 16000.0 / (512.0 * 340.4));
    for (int i = tid; i < CF; i += 1024) {
        int c = i / FDIM;
        int f = i - c * FDIM;
        float ph = coef * (float)f * (tdoa[c] - d0);
        float s, co;
        sincosf(ph, &s, &co);
        g_sv[i]      = co * 0.5f;   // / ||sv|| (= sqrt(C) = 2)
        g_sv[CF + i] = s * 0.5f;
    }
}

// ---------------------------------------------------------------------------
// STFT: 256-thr block = 4 FFT units (64 thr). One packed complex FFT (two
// real channels, one frame) per unit via 3 radix-8 register passes with a
// shared twiddle table (R2 structure). Epilogue: stage unpacked spectra to
// shared (stride-1, conflict-free) then fully vectorized float4 sweep that
// also broadcasts the steering-vector groups.
// ---------------------------------------------------------------------------
__global__ void __launch_bounds__(256) stft_kernel(const float* __restrict__ x,
                                                   float* __restrict__ out) {
    __shared__ c2 tw[NFFT];                       // tw[m] = exp(-2*pi*i*m/512)
    __shared__ c2 sd[4][520];                     // skewed: 8 rows of 65
    __shared__ __align__(16) float fin[4][1040];  // staged output per unit

    const int tid = threadIdx.x;

    for (int m = tid; m < NFFT; m += 256) {
        float ang = (float)(-2.0 * PI_D / (double)NFFT) * (float)m;
        float s, c; sincosf(ang, &s, &c);
        tw[m].x = c; tw[m].y = s;
    }
    __syncthreads();

    const int u   = tid >> 6;        // FFT unit 0..3
    const int tau = tid & 63;
    const int t   = blockIdx.x * 4 + u;
    const int by  = blockIdx.y;
    const int b   = by >> 1;
    const int pr  = by & 1;          // channel pair (2pr, 2pr+1)
    const bool active = (t < TT);

    c2 v[8], o8[8];

    // ---- pass 1: windowed load, radix-8 over n2, twiddle W64^{n1*k0} ----
    if (active) {
        const float* xa = x + (size_t)(b * CC + 2 * pr) * LSIG;
        const float* xb = xa + LSIG;
#pragma unroll
        for (int n2 = 0; n2 < 8; n2++) {
            int n = n2 * 64 + tau;
            int p = t * HOP + n - 256;                       // reflect pad
            int s = (p < 0) ? -p : ((p >= LSIG) ? 2 * LSIG - 2 - p : p);
            float w = 0.5f * (1.0f - tw[n].x);               // Hann
            v[n2].x = xa[s] * w;
            v[n2].y = xb[s] * w;
        }
        radix8(v, o8);
        int n1 = tau >> 3;
#pragma unroll
        for (int k0 = 0; k0 < 8; k0++) {
            c2 r = cmul(o8[k0], tw[(8 * n1 * k0) & 511]);
            sd[u][k0 * 65 + tau] = r;
        }
    }
    __syncthreads();

    // ---- pass 2: radix-8 over n1, twiddle W512^{n0*(8*k1+k0)} ----
    if (active) {
        int k0 = tau >> 3, n0 = tau & 7;
#pragma unroll
        for (int n1 = 0; n1 < 8; n1++) v[n1] = sd[u][k0 * 65 + n1 * 8 + n0];
        radix8(v, o8);
#pragma unroll
        for (int k1 = 0; k1 < 8; k1++) {
            c2 r = cmul(o8[k1], tw[(n0 * (8 * k1 + k0)) & 511]);
            sd[u][k0 * 65 + k1 * 8 + n0] = r;
        }
    }
    __syncthreads();

    // ---- pass 3: radix-8 over n0 -> natural order back into sd ----
    if (active) {
        int k0 = tau >> 3, k1 = tau & 7;
#pragma unroll
        for (int n0 = 0; n0 < 8; n0++) v[n0] = sd[u][k0 * 65 + k1 * 8 + n0];
        radix8(v, o8);
    }
    __syncthreads();
    if (active) {
        int k0 = tau >> 3, k1 = tau & 7;
#pragma unroll
        for (int k2 = 0; k2 < 8; k2++) sd[u][k2 * 64 + k1 * 8 + k0] = o8[k2];
    }
    __syncthreads();

    // ---- stage unpacked spectra into fin (stride-1, conflict-free) ----
    // fin layout (shift s = 2*pr keeps float4 alignment congruent with dst):
    //   [s + k]       A.re   [s + 257 + k] B.re      (re segment: 514)
    //   [s+520 + k]   A.im   [s + 777 + k] B.im      (im segment: 514)
    const int s = 2 * pr;
    if (active) {
        for (int k = tau; k <= 256; k += 64) {
            c2 zk = sd[u][k];
            c2 zm = sd[u][(512 - k) & 511];
            fin[u][s + k]       = 0.5f * (zk.x + zm.x);  // A.re
            fin[u][s + 257 + k] = 0.5f * (zk.y + zm.y);  // B.re
            fin[u][s + 520 + k] = 0.5f * (zk.y - zm.y);  // A.im
            fin[u][s + 777 + k] = 0.5f * (zm.x - zk.x);  // B.im
        }
    }
    __syncthreads();

    // ---- vectorized sweep: 4 segments of 514 floats each ----
    // seg0: X.re   seg1: X.im   seg2: SV.re   seg3: SV.im
    if (active) {
        float* row = out + ((size_t)b * TT + t) * KFEAT;
        const int off = 2 * pr * FDIM;     // off mod 4 == s
        const int h = s;                   // alignment head (0 or 2)
#pragma unroll
        for (int seg = 0; seg < 4; seg++) {
            float* dst = row + seg * CF + off;
            const float* src = (seg == 0) ? (fin[u] + s)
                             : (seg == 1) ? (fin[u] + s + 520)
                             : (seg == 2) ? (g_sv + off)
                                          : (g_sv + CF + off);
#pragma unroll
            for (int it = 0; it < 2; it++) {
                int i = tau + it * 64;     // 128 quads per segment
                int j = h + 4 * i;
                *reinterpret_cast<float4*>(dst + j) =
                    *reinterpret_cast<const float4*>(src + j);
            }
            if (tau < 2) {                 // exactly 2 scalars per segment
                int j = (h == 0) ? (512 + tau) : tau;
                dst[j] = src[j];
            }
        }
    }
}

// ---------------------------------------------------------------------------
extern "C" void kernel_launch(void* const* d_in, const int* in_sizes, int n_in,
                              void* d_out, int out_size) {
    const float* x     = (const float*)d_in[0];
    const float* angle = (const float*)d_in[1];
    const float* mic   = (const float*)d_in[2];
    float* out = (float*)d_out;

    prep_kernel<<<1, 1024>>>(angle, mic);

    dim3 grid((TT + 3) / 4, BB * 2);
    stft_kernel<<<grid, 256>>>(x, out);
}

// round 5
// speedup vs baseline: 1.4268x; 1.2409x over previous
#include <cuda_runtime.h>
#include <math.h>

#define NFFT 512
#define HOP  128
#define LSIG 160000
#define BB   16
#define CC   4
#define TT   1251
#define FDIM 257
#define KFEAT (4 * CC * FDIM)   // 4112
#define CF   (CC * FDIM)        // 1028

#define PI_D 3.14159265358979323846

struct c2 { float x, y; };

__device__ __forceinline__ c2 cmul(c2 a, c2 b){ c2 r; r.x = a.x*b.x - a.y*b.y; r.y = a.x*b.y + a.y*b.x; return r; }
__device__ __forceinline__ c2 cadd(c2 a, c2 b){ c2 r; r.x = a.x+b.x; r.y = a.y+b.y; return r; }
__device__ __forceinline__ c2 csub(c2 a, c2 b){ c2 r; r.x = a.x-b.x; r.y = a.y-b.y; return r; }
__device__ __forceinline__ c2 mulnegi(c2 a){ c2 r; r.x = a.y; r.y = -a.x; return r; }

// radix-8 DFT: o[k] = sum_j v[j] * w8^{j*k}, w8 = exp(-2*pi*i/8)
__device__ __forceinline__ void radix8(const c2* v, c2* o) {
    const float S = 0.70710678118654752f;
    c2 a0=cadd(v[0],v[4]), a1=csub(v[0],v[4]);
    c2 a2=cadd(v[2],v[6]), a3=csub(v[2],v[6]);
    c2 b0=cadd(v[1],v[5]), b1=csub(v[1],v[5]);
    c2 b2=cadd(v[3],v[7]), b3=csub(v[3],v[7]);
    c2 ia3 = mulnegi(a3), ib3 = mulnegi(b3);
    c2 c0=cadd(a0,a2), c1=csub(a0,a2);
    c2 e2=cadd(a1,ia3), e3=csub(a1,ia3);
    c2 d0=cadd(b0,b2), d1=csub(b0,b2);
    c2 d2=cadd(b1,ib3), d3=csub(b1,ib3);
    c2 w1d2; w1d2.x = S*(d2.x + d2.y); w1d2.y = S*(d2.y - d2.x);
    c2 w3d3; w3d3.x = S*(d3.y - d3.x); w3d3.y = -S*(d3.x + d3.y);
    c2 id1 = mulnegi(d1);
    o[0]=cadd(c0,d0);    o[4]=csub(c0,d0);
    o[2]=cadd(c1,id1);   o[6]=csub(c1,id1);
    o[1]=cadd(e2,w1d2);  o[5]=csub(e2,w1d2);
    o[3]=cadd(e3,w3d3);  o[7]=csub(e3,w3d3);
}

__device__ __align__(16) float g_sv[2 * CF];   // [0..CF)=cos/2, [CF..2CF)=sin/2

// ---------------------------------------------------------------------------
// Prep: TDOA + steering-vector table (single block, accurate trig)
// ---------------------------------------------------------------------------
__global__ void __launch_bounds__(1024) prep_kernel(const float* __restrict__ angle,
                                                    const float* __restrict__ mic_pos) {
    __shared__ float tdoa[CC];
    int tid = threadIdx.x;
    if (tid < CC) {
        const float half_pi = (float)(PI_D / 2.0);
        float sin90 = sinf(half_pi);   // fp32 quirks reproduced
        float cos90 = cosf(half_pi);
        float sum = 0.f;
        for (int b = 0; b < BB; b++) {
            float rad = -angle[b] * (float)(PI_D / 180.0);
            float lx = cosf(rad) * sin90;
            float ly = sinf(rad) * sin90;
            float lz = cos90;          // DIST = 1.0
            const float* mp = mic_pos + (b * CC + tid) * 3;
            float dx = mp[0] - lx, dy = mp[1] - ly, dz = mp[2] - lz;
            sum += dx * dx + dy * dy + dz * dz;
        }
        tdoa[tid] = sqrtf(sum);
    }
    __syncthreads();
    const float d0 = tdoa[0];
    const float coef = (float)(-2.0 * PI_D * 16000.0 / (512.0 * 340.4));
    for (int i = tid; i < CF; i += 1024) {
        int c = i / FDIM;
        int f = i - c * FDIM;
        float ph = coef * (float)f * (tdoa[c] - d0);
        float s, co;
        sincosf(ph, &s, &co);
        g_sv[i]      = co * 0.5f;   // / ||sv|| (= sqrt(C) = 2)
        g_sv[CF + i] = s * 0.5f;
    }
}

// ---------------------------------------------------------------------------
// STFT: 256-thr block = 4 FFT units (64 thr). One packed complex FFT (two
// real channels, one frame) per unit via 3 radix-8 register passes.
// Twiddles & window computed in registers (__sincosf + short cmul chains) —
// no shared twiddle table. Epilogue: R2's scalar coalesced store (optimal
// bytes/wavefront) fused with the steering-vector broadcast.
// ---------------------------------------------------------------------------
__global__ void __launch_bounds__(256) stft_kernel(const float* __restrict__ x,
                                                   float* __restrict__ out) {
    __shared__ c2 sd[4][520];     // skewed: 8 rows of 65 (64 + pad)
    __shared__ c2 nat[4][512];    // natural-order result

    const int tid = threadIdx.x;
    const int u   = tid >> 6;        // FFT unit 0..3
    const int tau = tid & 63;
    const int t   = blockIdx.x * 4 + u;
    const int by  = blockIdx.y;
    const int b   = by >> 1;
    const int pr  = by & 1;          // channel pair (2pr, 2pr+1)
    const bool active = (t < TT);

    c2 v[8], o8[8];

    // ---- pass 1: windowed load, radix-8 over n2, twiddle W64^{n1*k0} ----
    if (active) {
        const float S = 0.70710678118654752f;
        const float c8[8] = {1.f,  S, 0.f, -S, -1.f, -S,  0.f,  S};  // cos(pi*n2/4)
        const float s8[8] = {0.f,  S, 1.f,  S,  0.f, -S, -1.f, -S};  // sin(pi*n2/4)
        float sth, cth;
        __sincosf((float)(2.0 * PI_D / 512.0) * (float)tau, &sth, &cth);

        const float* xa = x + (size_t)(b * CC + 2 * pr) * LSIG;
        const float* xb = xa + LSIG;
#pragma unroll
        for (int n2 = 0; n2 < 8; n2++) {
            int n = n2 * 64 + tau;
            int p = t * HOP + n - 256;                       // reflect pad
            int s = (p < 0) ? -p : ((p >= LSIG) ? 2 * LSIG - 2 - p : p);
            float cosn = c8[n2] * cth - s8[n2] * sth;        // cos(2*pi*n/512)
            float w = 0.5f - 0.5f * cosn;                    // Hann
            v[n2].x = xa[s] * w;
            v[n2].y = xb[s] * w;
        }
        radix8(v, o8);
        int n1 = tau >> 3;
        float ss, cs;
        __sincosf((float)(-2.0 * PI_D / 64.0) * (float)n1, &ss, &cs);
        c2 step; step.x = cs; step.y = ss;                   // W64^{n1}
        c2 w; w.x = 1.f; w.y = 0.f;
#pragma unroll
        for (int k0 = 0; k0 < 8; k0++) {
            sd[u][k0 * 65 + tau] = cmul(o8[k0], w);          // * W64^{n1*k0}
            w = cmul(w, step);
        }
    }
    __syncthreads();

    // ---- pass 2: radix-8 over n1, twiddle W512^{n0*k0} * W64^{n0*k1} ----
    if (active) {
        int k0 = tau >> 3, n0 = tau & 7;
#pragma unroll
        for (int n1 = 0; n1 < 8; n1++) v[n1] = sd[u][k0 * 65 + n1 * 8 + n0];
        radix8(v, o8);
        float s0, c0, ss, cs;
        __sincosf((float)(-2.0 * PI_D / 512.0) * (float)(n0 * k0), &s0, &c0);
        __sincosf((float)(-2.0 * PI_D / 64.0) * (float)n0, &ss, &cs);
        c2 w;    w.x = c0;   w.y = s0;                       // W512^{n0*k0}
        c2 step; step.x = cs; step.y = ss;                   // W64^{n0}
#pragma unroll
        for (int k1 = 0; k1 < 8; k1++) {
            sd[u][k0 * 65 + k1 * 8 + n0] = cmul(o8[k1], w);
            w = cmul(w, step);
        }
    }
    __syncthreads();

    // ---- pass 3: radix-8 over n0 -> nat[64*k2 + 8*k1 + k0] ----
    // (reads sd, writes nat: different buffers, no intermediate barrier)
    if (active) {
        int k0 = tau >> 3, k1 = tau & 7;
#pragma unroll
        for (int n0 = 0; n0 < 8; n0++) v[n0] = sd[u][k0 * 65 + k1 * 8 + n0];
        radix8(v, o8);
#pragma unroll
        for (int k2 = 0; k2 < 8; k2++) nat[u][k2 * 64 + k1 * 8 + k0] = o8[k2];
    }
    __syncthreads();

    // ---- unpack 2 real spectra + write X groups + SV groups (coalesced) ----
    if (active) {
        float* row = out + ((size_t)b * TT + t) * KFEAT;
        const int ca = 2 * pr, cb = 2 * pr + 1;
        float* aBase = row + ca * FDIM;
        float* bBase = row + cb * FDIM;
        for (int k = tau; k <= 256; k += 64) {
            c2 zk = nat[u][k];
            c2 zm = nat[u][(512 - k) & 511];
            aBase[k]          = 0.5f * (zk.x + zm.x);   // A.re
            aBase[CF + k]     = 0.5f * (zk.y - zm.y);   // A.im
            bBase[k]          = 0.5f * (zk.y + zm.y);   // B.re
            bBase[CF + k]     = 0.5f * (zm.x - zk.x);   // B.im
            int ia = ca * FDIM + k, ib = cb * FDIM + k;
            aBase[2 * CF + k] = __ldg(&g_sv[ia]);
            aBase[3 * CF + k] = __ldg(&g_sv[CF + ia]);
            bBase[2 * CF + k] = __ldg(&g_sv[ib]);
            bBase[3 * CF + k] = __ldg(&g_sv[CF + ib]);
        }
    }
}

// ---------------------------------------------------------------------------
extern "C" void kernel_launch(void* const* d_in, const int* in_sizes, int n_in,
                              void* d_out, int out_size) {
    const float* x     = (const float*)d_in[0];
    const float* angle = (const float*)d_in[1];
    const float* mic   = (const float*)d_in[2];
    float* out = (float*)d_out;

    prep_kernel<<<1, 1024>>>(angle, mic);

    dim3 grid((TT + 3) / 4, BB * 2);
    stft_kernel<<<grid, 256>>>(x, out);
}

// round 6
// speedup vs baseline: 1.4478x; 1.0147x over previous
#include <cuda_runtime.h>
#include <math.h>

#define NFFT 512
#define HOP  128
#define LSIG 160000
#define BB   16
#define CC   4
#define TT   1251
#define FDIM 257
#define KFEAT (4 * CC * FDIM)   // 4112
#define CF   (CC * FDIM)        // 1028

#define PI_D 3.14159265358979323846

struct c2 { float x, y; };

__device__ __forceinline__ c2 cmul(c2 a, c2 b){ c2 r; r.x = a.x*b.x - a.y*b.y; r.y = a.x*b.y + a.y*b.x; return r; }
__device__ __forceinline__ c2 cadd(c2 a, c2 b){ c2 r; r.x = a.x+b.x; r.y = a.y+b.y; return r; }
__device__ __forceinline__ c2 csub(c2 a, c2 b){ c2 r; r.x = a.x-b.x; r.y = a.y-b.y; return r; }
__device__ __forceinline__ c2 mulnegi(c2 a){ c2 r; r.x = a.y; r.y = -a.x; return r; }

// radix-8 DFT: o[k] = sum_j v[j] * w8^{j*k}, w8 = exp(-2*pi*i/8)
__device__ __forceinline__ void radix8(const c2* v, c2* o) {
    const float S = 0.70710678118654752f;
    c2 a0=cadd(v[0],v[4]), a1=csub(v[0],v[4]);
    c2 a2=cadd(v[2],v[6]), a3=csub(v[2],v[6]);
    c2 b0=cadd(v[1],v[5]), b1=csub(v[1],v[5]);
    c2 b2=cadd(v[3],v[7]), b3=csub(v[3],v[7]);
    c2 ia3 = mulnegi(a3), ib3 = mulnegi(b3);
    c2 c0=cadd(a0,a2), c1=csub(a0,a2);
    c2 e2=cadd(a1,ia3), e3=csub(a1,ia3);
    c2 d0=cadd(b0,b2), d1=csub(b0,b2);
    c2 d2=cadd(b1,ib3), d3=csub(b1,ib3);
    c2 w1d2; w1d2.x = S*(d2.x + d2.y); w1d2.y = S*(d2.y - d2.x);
    c2 w3d3; w3d3.x = S*(d3.y - d3.x); w3d3.y = -S*(d3.x + d3.y);
    c2 id1 = mulnegi(d1);
    o[0]=cadd(c0,d0);    o[4]=csub(c0,d0);
    o[2]=cadd(c1,id1);   o[6]=csub(c1,id1);
    o[1]=cadd(e2,w1d2);  o[5]=csub(e2,w1d2);
    o[3]=cadd(e3,w3d3);  o[7]=csub(e3,w3d3);
}

__device__ __align__(16) float g_sv[2 * CF];   // [0..CF)=cos/2, [CF..2CF)=sin/2

// ---------------------------------------------------------------------------
// Prep: TDOA + steering-vector table (single block, accurate trig)
// ---------------------------------------------------------------------------
__global__ void __launch_bounds__(1024) prep_kernel(const float* __restrict__ angle,
                                                    const float* __restrict__ mic_pos) {
    __shared__ float tdoa[CC];
    int tid = threadIdx.x;
    if (tid < CC) {
        const float half_pi = (float)(PI_D / 2.0);
        float sin90 = sinf(half_pi);   // fp32 quirks reproduced
        float cos90 = cosf(half_pi);
        float sum = 0.f;
        for (int b = 0; b < BB; b++) {
            float rad = -angle[b] * (float)(PI_D / 180.0);
            float lx = cosf(rad) * sin90;
            float ly = sinf(rad) * sin90;
            float lz = cos90;          // DIST = 1.0
            const float* mp = mic_pos + (b * CC + tid) * 3;
            float dx = mp[0] - lx, dy = mp[1] - ly, dz = mp[2] - lz;
            sum += dx * dx + dy * dy + dz * dz;
        }
        tdoa[tid] = sqrtf(sum);
    }
    __syncthreads();
    const float d0 = tdoa[0];
    const float coef = (float)(-2.0 * PI_D * 16000.0 / (512.0 * 340.4));
    for (int i = tid; i < CF; i += 1024) {
        int c = i / FDIM;
        int f = i - c * FDIM;
        float ph = coef * (float)f * (tdoa[c] - d0);
        float s, co;
        sincosf(ph, &s, &co);
        g_sv[i]      = co * 0.5f;   // / ||sv|| (= sqrt(C) = 2)
        g_sv[CF + i] = s * 0.5f;
    }
}

// ---------------------------------------------------------------------------
// STFT: 256-thr block = 4 FFT units (64 thr). One packed complex FFT (two
// real channels, one frame) per unit via 3 radix-8 register passes.
// Twiddles & window computed in registers (__sincosf + short cmul chains) —
// no shared twiddle table. Epilogue: R2's scalar coalesced store (optimal
// bytes/wavefront) fused with the steering-vector broadcast.
// ---------------------------------------------------------------------------
__global__ void __launch_bounds__(256) stft_kernel(const float* __restrict__ x,
                                                   float* __restrict__ out) {
    __shared__ c2 sd[4][520];     // skewed: 8 rows of 65 (64 + pad)
    __shared__ c2 nat[4][512];    // natural-order result

    const int tid = threadIdx.x;
    const int u   = tid >> 6;        // FFT unit 0..3
    const int tau = tid & 63;
    const int t   = blockIdx.x * 4 + u;
    const int by  = blockIdx.y;
    const int b   = by >> 1;
    const int pr  = by & 1;          // channel pair (2pr, 2pr+1)
    const bool active = (t < TT);

    c2 v[8], o8[8];

    // ---- pass 1: windowed load, radix-8 over n2, twiddle W64^{n1*k0} ----
    if (active) {
        const float S = 0.70710678118654752f;
        const float c8[8] = {1.f,  S, 0.f, -S, -1.f, -S,  0.f,  S};  // cos(pi*n2/4)
        const float s8[8] = {0.f,  S, 1.f,  S,  0.f, -S, -1.f, -S};  // sin(pi*n2/4)
        float sth, cth;
        __sincosf((float)(2.0 * PI_D / 512.0) * (float)tau, &sth, &cth);

        const float* xa = x + (size_t)(b * CC + 2 * pr) * LSIG;
        const float* xb = xa + LSIG;
#pragma unroll
        for (int n2 = 0; n2 < 8; n2++) {
            int n = n2 * 64 + tau;
            int p = t * HOP + n - 256;                       // reflect pad
            int s = (p < 0) ? -p : ((p >= LSIG) ? 2 * LSIG - 2 - p : p);
            float cosn = c8[n2] * cth - s8[n2] * sth;        // cos(2*pi*n/512)
            float w = 0.5f - 0.5f * cosn;                    // Hann
            v[n2].x = xa[s] * w;
            v[n2].y = xb[s] * w;
        }
        radix8(v, o8);
        int n1 = tau >> 3;
        float ss, cs;
        __sincosf((float)(-2.0 * PI_D / 64.0) * (float)n1, &ss, &cs);
        c2 step; step.x = cs; step.y = ss;                   // W64^{n1}
        c2 w; w.x = 1.f; w.y = 0.f;
#pragma unroll
        for (int k0 = 0; k0 < 8; k0++) {
            sd[u][k0 * 65 + tau] = cmul(o8[k0], w);          // * W64^{n1*k0}
            w = cmul(w, step);
        }
    }
    __syncthreads();

    // ---- pass 2: radix-8 over n1, twiddle W512^{n0*k0} * W64^{n0*k1} ----
    if (active) {
        int k0 = tau >> 3, n0 = tau & 7;
#pragma unroll
        for (int n1 = 0; n1 < 8; n1++) v[n1] = sd[u][k0 * 65 + n1 * 8 + n0];
        radix8(v, o8);
        float s0, c0, ss, cs;
        __sincosf((float)(-2.0 * PI_D / 512.0) * (float)(n0 * k0), &s0, &c0);
        __sincosf((float)(-2.0 * PI_D / 64.0) * (float)n0, &ss, &cs);
        c2 w;    w.x = c0;   w.y = s0;                       // W512^{n0*k0}
        c2 step; step.x = cs; step.y = ss;                   // W64^{n0}
#pragma unroll
        for (int k1 = 0; k1 < 8; k1++) {
            sd[u][k0 * 65 + k1 * 8 + n0] = cmul(o8[k1], w);
            w = cmul(w, step);
        }
    }
    __syncthreads();

    // ---- pass 3: radix-8 over n0 -> nat[64*k2 + 8*k1 + k0] ----
    // (reads sd, writes nat: different buffers, no intermediate barrier)
    if (active) {
        int k0 = tau >> 3, k1 = tau & 7;
#pragma unroll
        for (int n0 = 0; n0 < 8; n0++) v[n0] = sd[u][k0 * 65 + k1 * 8 + n0];
        radix8(v, o8);
#pragma unroll
        for (int k2 = 0; k2 < 8; k2++) nat[u][k2 * 64 + k1 * 8 + k0] = o8[k2];
    }
    __syncthreads();

    // ---- unpack 2 real spectra + write X groups + SV groups (coalesced) ----
    if (active) {
        float* row = out + ((size_t)b * TT + t) * KFEAT;
        const int ca = 2 * pr, cb = 2 * pr + 1;
        float* aBase = row + ca * FDIM;
        float* bBase = row + cb * FDIM;
        for (int k = tau; k <= 256; k += 64) {
            c2 zk = nat[u][k];
            c2 zm = nat[u][(512 - k) & 511];
            aBase[k]          = 0.5f * (zk.x + zm.x);   // A.re
            aBase[CF + k]     = 0.5f * (zk.y - zm.y);   // A.im
            bBase[k]          = 0.5f * (zk.y + zm.y);   // B.re
            bBase[CF + k]     = 0.5f * (zm.x - zk.x);   // B.im
            int ia = ca * FDIM + k, ib = cb * FDIM + k;
            aBase[2 * CF + k] = __ldg(&g_sv[ia]);
            aBase[3 * CF + k] = __ldg(&g_sv[CF + ia]);
            bBase[2 * CF + k] = __ldg(&g_sv[ib]);
            bBase[3 * CF + k] = __ldg(&g_sv[CF + ib]);
        }
    }
}

// ---------------------------------------------------------------------------
extern "C" void kernel_launch(void* const* d_in, const int* in_sizes, int n_in,
                              void* d_out, int out_size) {
    const float* x     = (const float*)d_in[0];
    const float* angle = (const float*)d_in[1];
    const float* mic   = (const float*)d_in[2];
    float* out = (float*)d_out;

    prep_kernel<<<1, 1024>>>(angle, mic);

    dim3 grid((TT + 3) / 4, BB * 2);
    stft_kernel<<<grid, 256>>>(x, out);
}

// round 7
// speedup vs baseline: 1.6686x; 1.1525x over previous
#include <cuda_runtime.h>
#include <math.h>

#define NFFT 512
#define HOP  128
#define LSIG 160000
#define BB   16
#define CC   4
#define TT   1251
#define FDIM 257
#define KFEAT (4 * CC * FDIM)   // 4112
#define CF   (CC * FDIM)        // 1028

#define PI_D 3.14159265358979323846

struct c2 { float x, y; };

__device__ __forceinline__ c2 cmul(c2 a, c2 b){ c2 r; r.x = a.x*b.x - a.y*b.y; r.y = a.x*b.y + a.y*b.x; return r; }
__device__ __forceinline__ c2 cadd(c2 a, c2 b){ c2 r; r.x = a.x+b.x; r.y = a.y+b.y; return r; }
__device__ __forceinline__ c2 csub(c2 a, c2 b){ c2 r; r.x = a.x-b.x; r.y = a.y-b.y; return r; }
__device__ __forceinline__ c2 mulnegi(c2 a){ c2 r; r.x = a.y; r.y = -a.x; return r; }

// radix-8 DFT: o[k] = sum_j v[j] * w8^{j*k}, w8 = exp(-2*pi*i/8)
__device__ __forceinline__ void radix8(const c2* v, c2* o) {
    const float S = 0.70710678118654752f;
    c2 a0=cadd(v[0],v[4]), a1=csub(v[0],v[4]);
    c2 a2=cadd(v[2],v[6]), a3=csub(v[2],v[6]);
    c2 b0=cadd(v[1],v[5]), b1=csub(v[1],v[5]);
    c2 b2=cadd(v[3],v[7]), b3=csub(v[3],v[7]);
    c2 ia3 = mulnegi(a3), ib3 = mulnegi(b3);
    c2 c0=cadd(a0,a2), c1=csub(a0,a2);
    c2 e2=cadd(a1,ia3), e3=csub(a1,ia3);
    c2 d0=cadd(b0,b2), d1=csub(b0,b2);
    c2 d2=cadd(b1,ib3), d3=csub(b1,ib3);
    c2 w1d2; w1d2.x = S*(d2.x + d2.y); w1d2.y = S*(d2.y - d2.x);
    c2 w3d3; w3d3.x = S*(d3.y - d3.x); w3d3.y = -S*(d3.x + d3.y);
    c2 id1 = mulnegi(d1);
    o[0]=cadd(c0,d0);    o[4]=csub(c0,d0);
    o[2]=cadd(c1,id1);   o[6]=csub(c1,id1);
    o[1]=cadd(e2,w1d2);  o[5]=csub(e2,w1d2);
    o[3]=cadd(e3,w3d3);  o[7]=csub(e3,w3d3);
}

__device__ __align__(16) float g_sv[2 * CF];   // [0..CF)=cos/2, [CF..2CF)=sin/2

// ---------------------------------------------------------------------------
// Prep: TDOA + steering-vector table (single block, accurate trig)
// ---------------------------------------------------------------------------
__global__ void __launch_bounds__(1024) prep_kernel(const float* __restrict__ angle,
                                                    const float* __restrict__ mic_pos) {
    __shared__ float tdoa[CC];
    int tid = threadIdx.x;
    if (tid < CC) {
        const float half_pi = (float)(PI_D / 2.0);
        float sin90 = sinf(half_pi);   // fp32 quirks reproduced
        float cos90 = cosf(half_pi);
        float sum = 0.f;
        for (int b = 0; b < BB; b++) {
            float rad = -angle[b] * (float)(PI_D / 180.0);
            float lx = cosf(rad) * sin90;
            float ly = sinf(rad) * sin90;
            float lz = cos90;          // DIST = 1.0
            const float* mp = mic_pos + (b * CC + tid) * 3;
            float dx = mp[0] - lx, dy = mp[1] - ly, dz = mp[2] - lz;
            sum += dx * dx + dy * dy + dz * dz;
        }
        tdoa[tid] = sqrtf(sum);
    }
    __syncthreads();
    const float d0 = tdoa[0];
    const float coef = (float)(-2.0 * PI_D * 16000.0 / (512.0 * 340.4));
    for (int i = tid; i < CF; i += 1024) {
        int c = i / FDIM;
        int f = i - c * FDIM;
        float ph = coef * (float)f * (tdoa[c] - d0);
        float s, co;
        sincosf(ph, &s, &co);
        g_sv[i]      = co * 0.5f;   // / ||sv|| (= sqrt(C) = 2)
        g_sv[CF + i] = s * 0.5f;
    }
}

// ---------------------------------------------------------------------------
// STFT: 256-thr block = 4 FFT units (64 thr). One packed complex FFT (two
// real channels, one frame) per unit via 3 radix-8 register passes.
// Twiddles in registers; pass2->pass3 exchange done as an in-register 8x8
// XOR-transpose (shfl_xor within 8-lane groups) instead of shared memory.
// ---------------------------------------------------------------------------
__global__ void __launch_bounds__(256) stft_kernel(const float* __restrict__ x,
                                                   float* __restrict__ out) {
    __shared__ c2 sd[4][520];     // skewed: 8 rows of 65 (pass1 -> pass2 only)
    __shared__ c2 nat[4][512];    // natural-order result

    const int tid = threadIdx.x;
    const int u   = tid >> 6;        // FFT unit 0..3
    const int tau = tid & 63;
    const int t   = blockIdx.x * 4 + u;
    const int by  = blockIdx.y;
    const int b   = by >> 1;
    const int pr  = by & 1;          // channel pair (2pr, 2pr+1)
    const bool active = (t < TT);

    c2 v[8], o8[8];

    // ---- pass 1: windowed load, radix-8 over n2, twiddle W64^{n1*k0} ----
    if (active) {
        const float S = 0.70710678118654752f;
        const float c8[8] = {1.f,  S, 0.f, -S, -1.f, -S,  0.f,  S};
        const float s8[8] = {0.f,  S, 1.f,  S,  0.f, -S, -1.f, -S};
        float sth, cth;
        __sincosf((float)(2.0 * PI_D / 512.0) * (float)tau, &sth, &cth);

        const float* xa = x + (size_t)(b * CC + 2 * pr) * LSIG;
        const float* xb = xa + LSIG;
#pragma unroll
        for (int n2 = 0; n2 < 8; n2++) {
            int n = n2 * 64 + tau;
            int p = t * HOP + n - 256;                       // reflect pad
            int s = (p < 0) ? -p : ((p >= LSIG) ? 2 * LSIG - 2 - p : p);
            float cosn = c8[n2] * cth - s8[n2] * sth;        // cos(2*pi*n/512)
            float w = 0.5f - 0.5f * cosn;                    // Hann
            v[n2].x = xa[s] * w;
            v[n2].y = xb[s] * w;
        }
        radix8(v, o8);
        int n1 = tau >> 3;
        float ss, cs;
        __sincosf((float)(-2.0 * PI_D / 64.0) * (float)n1, &ss, &cs);
        c2 step; step.x = cs; step.y = ss;                   // W64^{n1}
        c2 w; w.x = 1.f; w.y = 0.f;
#pragma unroll
        for (int k0 = 0; k0 < 8; k0++) {
            sd[u][k0 * 65 + tau] = cmul(o8[k0], w);          // * W64^{n1*k0}
            w = cmul(w, step);
        }
    }
    __syncthreads();

    // ---- pass 2 + 3 fused: radix-8 over n1, twiddle, SHFL transpose,
    //      radix-8 over n0, store natural order ----
    if (active) {
        const int k0 = tau >> 3;
        const int l  = tau & 7;      // = n0 in pass 2, = k1 in pass 3
#pragma unroll
        for (int n1 = 0; n1 < 8; n1++) v[n1] = sd[u][k0 * 65 + n1 * 8 + l];
        radix8(v, o8);
        {   // twiddle W512^{n0*k0} * W64^{n0*k1},  n0 = l
            float s0, c0, ss, cs;
            __sincosf((float)(-2.0 * PI_D / 512.0) * (float)(l * k0), &s0, &c0);
            __sincosf((float)(-2.0 * PI_D / 64.0) * (float)l, &ss, &cs);
            c2 w;    w.x = c0;   w.y = s0;
            c2 step; step.x = cs; step.y = ss;
#pragma unroll
            for (int k1 = 0; k1 < 8; k1++) {
                o8[k1] = cmul(o8[k1], w);
                w = cmul(w, step);
            }
        }
        // 8x8 XOR-transpose within the 8-lane group (same k0):
        // before: lane l = n0 holds o8[k1];  after: lane l = k1 holds o8[n0]
#pragma unroll
        for (int s = 1; s < 8; s <<= 1) {
#pragma unroll
            for (int j0 = 0; j0 < 8; j0++) {
                if (j0 & s) continue;
                const int j1 = j0 | s;
                c2 a = (l & s) ? o8[j0] : o8[j1];
                c2 bq;
                bq.x = __shfl_xor_sync(0xFFFFFFFFu, a.x, s);
                bq.y = __shfl_xor_sync(0xFFFFFFFFu, a.y, s);
                if (l & s) o8[j0] = bq; else o8[j1] = bq;
            }
        }
        // pass 3: radix-8 over n0; output X[64*k2 + 8*k1 + k0], k1 = l
        radix8(o8, v);
#pragma unroll
        for (int k2 = 0; k2 < 8; k2++) nat[u][k2 * 64 + l * 8 + k0] = v[k2];
    }
    __syncthreads();

    // ---- unpack 2 real spectra + write X groups + SV groups (coalesced) ----
    if (active) {
        float* row = out + ((size_t)b * TT + t) * KFEAT;
        const int ca = 2 * pr, cb = 2 * pr + 1;
        float* aBase = row + ca * FDIM;
        float* bBase = row + cb * FDIM;
        for (int k = tau; k <= 256; k += 64) {
            c2 zk = nat[u][k];
            c2 zm = nat[u][(512 - k) & 511];
            aBase[k]          = 0.5f * (zk.x + zm.x);   // A.re
            aBase[CF + k]     = 0.5f * (zk.y - zm.y);   // A.im
            bBase[k]          = 0.5f * (zk.y + zm.y);   // B.re
            bBase[CF + k]     = 0.5f * (zm.x - zk.x);   // B.im
            int ia = ca * FDIM + k, ib = cb * FDIM + k;
            aBase[2 * CF + k] = __ldg(&g_sv[ia]);
            aBase[3 * CF + k] = __ldg(&g_sv[CF + ia]);
            bBase[2 * CF + k] = __ldg(&g_sv[ib]);
            bBase[3 * CF + k] = __ldg(&g_sv[CF + ib]);
        }
    }
}

// ---------------------------------------------------------------------------
extern "C" void kernel_launch(void* const* d_in, const int* in_sizes, int n_in,
                              void* d_out, int out_size) {
    const float* x     = (const float*)d_in[0];
    const float* angle = (const float*)d_in[1];
    const float* mic   = (const float*)d_in[2];
    float* out = (float*)d_out;

    prep_kernel<<<1, 1024>>>(angle, mic);

    dim3 grid((TT + 3) / 4, BB * 2);
    stft_kernel<<<grid, 256>>>(x, out);
}

// round 8
// speedup vs baseline: 1.8775x; 1.1252x over previous
#include <cuda_runtime.h>
#include <math.h>

#define NFFT 512
#define HOP  128
#define LSIG 160000
#define BB   16
#define CC   4
#define TT   1251
#define FDIM 257
#define KFEAT (4 * CC * FDIM)   // 4112
#define CF   (CC * FDIM)        // 1028

#define PI_D 3.14159265358979323846
#define SVCOEF ((float)(-2.0 * PI_D * 16000.0 / (512.0 * 340.4)))

struct c2 { float x, y; };

__device__ __forceinline__ c2 cmul(c2 a, c2 b){ c2 r; r.x = a.x*b.x - a.y*b.y; r.y = a.x*b.y + a.y*b.x; return r; }
__device__ __forceinline__ c2 cadd(c2 a, c2 b){ c2 r; r.x = a.x+b.x; r.y = a.y+b.y; return r; }
__device__ __forceinline__ c2 csub(c2 a, c2 b){ c2 r; r.x = a.x-b.x; r.y = a.y-b.y; return r; }
__device__ __forceinline__ c2 mulnegi(c2 a){ c2 r; r.x = a.y; r.y = -a.x; return r; }

// radix-8 DFT: o[k] = sum_j v[j] * w8^{j*k}, w8 = exp(-2*pi*i/8)
__device__ __forceinline__ void radix8(const c2* v, c2* o) {
    const float S = 0.70710678118654752f;
    c2 a0=cadd(v[0],v[4]), a1=csub(v[0],v[4]);
    c2 a2=cadd(v[2],v[6]), a3=csub(v[2],v[6]);
    c2 b0=cadd(v[1],v[5]), b1=csub(v[1],v[5]);
    c2 b2=cadd(v[3],v[7]), b3=csub(v[3],v[7]);
    c2 ia3 = mulnegi(a3), ib3 = mulnegi(b3);
    c2 c0=cadd(a0,a2), c1=csub(a0,a2);
    c2 e2=cadd(a1,ia3), e3=csub(a1,ia3);
    c2 d0=cadd(b0,b2), d1=csub(b0,b2);
    c2 d2=cadd(b1,ib3), d3=csub(b1,ib3);
    c2 w1d2; w1d2.x = S*(d2.x + d2.y); w1d2.y = S*(d2.y - d2.x);
    c2 w3d3; w3d3.x = S*(d3.y - d3.x); w3d3.y = -S*(d3.x + d3.y);
    c2 id1 = mulnegi(d1);
    o[0]=cadd(c0,d0);    o[4]=csub(c0,d0);
    o[2]=cadd(c1,id1);   o[6]=csub(c1,id1);
    o[1]=cadd(e2,w1d2);  o[5]=csub(e2,w1d2);
    o[3]=cadd(e3,w3d3);  o[7]=csub(e3,w3d3);
}

__device__ float g_dt[CC];   // tdoa[c] - tdoa[0]

// ---------------------------------------------------------------------------
// Prep: TDOA only (64 threads, one accurate trig pair each, smem reduce)
// ---------------------------------------------------------------------------
__global__ void prep_kernel(const float* __restrict__ angle,
                            const float* __restrict__ mic_pos) {
    __shared__ float d2[BB * CC];
    const int tid = threadIdx.x;           // 64 threads: tid = b*CC + c
    const int b = tid >> 2;
    const float half_pi = (float)(PI_D / 2.0);
    float sin90 = sinf(half_pi);           // fp32 quirks reproduced
    float cos90 = cosf(half_pi);
    float rad = -angle[b] * (float)(PI_D / 180.0);
    float lx = cosf(rad) * sin90;
    float ly = sinf(rad) * sin90;
    float lz = cos90;                      // DIST = 1.0
    const float* mp = mic_pos + tid * 3;
    float dx = mp[0] - lx, dy = mp[1] - ly, dz = mp[2] - lz;
    d2[tid] = dx * dx + dy * dy + dz * dz;
    __syncthreads();
    if (tid < CC) {
        float s = 0.f;
        for (int bb = 0; bb < BB; bb++) s += d2[bb * CC + tid];
        d2[tid] = sqrtf(s);                // reuse as tdoa[c]
    }
    __syncthreads();
    if (tid < CC) g_dt[tid] = d2[tid] - d2[0];
}

// ---------------------------------------------------------------------------
// STFT: 256-thr block = 4 FFT units (64 thr). One packed complex FFT (two
// real channels, one frame) per unit via 3 radix-8 register passes.
// Twiddles in registers; pass2->pass3 exchange via in-register 8x8 XOR
// transpose (shfl). Epilogue recomputes the steering vector with __sincosf
// (no table loads) and writes all 4 feature groups coalesced.
// ---------------------------------------------------------------------------
__global__ void __launch_bounds__(256) stft_kernel(const float* __restrict__ x,
                                                   float* __restrict__ out) {
    __shared__ c2 sd[4][520];     // skewed: 8 rows of 65 (pass1 -> pass2 only)
    __shared__ c2 nat[4][512];    // natural-order result

    const int tid = threadIdx.x;
    const int u   = tid >> 6;        // FFT unit 0..3
    const int tau = tid & 63;
    const int t   = blockIdx.x * 4 + u;
    const int by  = blockIdx.y;
    const int b   = by >> 1;
    const int pr  = by & 1;          // channel pair (2pr, 2pr+1)
    const bool active = (t < TT);

    c2 v[8], o8[8];

    // ---- pass 1: windowed load, radix-8 over n2, twiddle W64^{n1*k0} ----
    if (active) {
        const float S = 0.70710678118654752f;
        const float c8[8] = {1.f,  S, 0.f, -S, -1.f, -S,  0.f,  S};
        const float s8[8] = {0.f,  S, 1.f,  S,  0.f, -S, -1.f, -S};
        float sth, cth;
        __sincosf((float)(2.0 * PI_D / 512.0) * (float)tau, &sth, &cth);

        const float* xa = x + (size_t)(b * CC + 2 * pr) * LSIG;
        const float* xb = xa + LSIG;
#pragma unroll
        for (int n2 = 0; n2 < 8; n2++) {
            int n = n2 * 64 + tau;
            int p = t * HOP + n - 256;                       // reflect pad
            int s = (p < 0) ? -p : ((p >= LSIG) ? 2 * LSIG - 2 - p : p);
            float cosn = c8[n2] * cth - s8[n2] * sth;        // cos(2*pi*n/512)
            float w = 0.5f - 0.5f * cosn;                    // Hann
            v[n2].x = xa[s] * w;
            v[n2].y = xb[s] * w;
        }
        radix8(v, o8);
        int n1 = tau >> 3;
        float ss, cs;
        __sincosf((float)(-2.0 * PI_D / 64.0) * (float)n1, &ss, &cs);
        c2 step; step.x = cs; step.y = ss;                   // W64^{n1}
        c2 w; w.x = 1.f; w.y = 0.f;
#pragma unroll
        for (int k0 = 0; k0 < 8; k0++) {
            sd[u][k0 * 65 + tau] = cmul(o8[k0], w);          // * W64^{n1*k0}
            w = cmul(w, step);
        }
    }
    __syncthreads();

    // ---- pass 2 + 3 fused: radix-8 over n1, twiddle, SHFL transpose,
    //      radix-8 over n0, store natural order ----
    if (active) {
        const int k0 = tau >> 3;
        const int l  = tau & 7;      // = n0 in pass 2, = k1 in pass 3
#pragma unroll
        for (int n1 = 0; n1 < 8; n1++) v[n1] = sd[u][k0 * 65 + n1 * 8 + l];
        radix8(v, o8);
        {   // twiddle W512^{n0*k0} * W64^{n0*k1},  n0 = l
            float s0, c0, ss, cs;
            __sincosf((float)(-2.0 * PI_D / 512.0) * (float)(l * k0), &s0, &c0);
            __sincosf((float)(-2.0 * PI_D / 64.0) * (float)l, &ss, &cs);
            c2 w;    w.x = c0;   w.y = s0;
            c2 step; step.x = cs; step.y = ss;
#pragma unroll
            for (int k1 = 0; k1 < 8; k1++) {
                o8[k1] = cmul(o8[k1], w);
                w = cmul(w, step);
            }
        }
        // 8x8 XOR-transpose within the 8-lane group (same k0):
        // before: lane l = n0 holds o8[k1];  after: lane l = k1 holds o8[n0]
#pragma unroll
        for (int s = 1; s < 8; s <<= 1) {
#pragma unroll
            for (int j0 = 0; j0 < 8; j0++) {
                if (j0 & s) continue;
                const int j1 = j0 | s;
                c2 a = (l & s) ? o8[j0] : o8[j1];
                c2 bq;
                bq.x = __shfl_xor_sync(0xFFFFFFFFu, a.x, s);
                bq.y = __shfl_xor_sync(0xFFFFFFFFu, a.y, s);
                if (l & s) o8[j0] = bq; else o8[j1] = bq;
            }
        }
        // pass 3: radix-8 over n0; output X[64*k2 + 8*k1 + k0], k1 = l
        radix8(o8, v);
#pragma unroll
        for (int k2 = 0; k2 < 8; k2++) nat[u][k2 * 64 + l * 8 + k0] = v[k2];
    }
    __syncthreads();

    // ---- unpack 2 real spectra + write X groups + computed SV groups ----
    if (active) {
        float* row = out + ((size_t)b * TT + t) * KFEAT;
        const int ca = 2 * pr, cb = 2 * pr + 1;
        const float dta = g_dt[ca];
        const float dtb = g_dt[cb];
        float* aBase = row + ca * FDIM;
        float* bBase = row + cb * FDIM;
        for (int k = tau; k <= 256; k += 64) {
            c2 zk = nat[u][k];
            c2 zm = nat[u][(512 - k) & 511];
            aBase[k]          = 0.5f * (zk.x + zm.x);   // A.re
            aBase[CF + k]     = 0.5f * (zk.y - zm.y);   // A.im
            bBase[k]          = 0.5f * (zk.y + zm.y);   // B.re
            bBase[CF + k]     = 0.5f * (zm.x - zk.x);   // B.im
            float sa, cA, sb, cB;
            __sincosf(SVCOEF * (float)k * dta, &sa, &cA);
            __sincosf(SVCOEF * (float)k * dtb, &sb, &cB);
            aBase[2 * CF + k] = 0.5f * cA;              // sv.re / ||sv||
            aBase[3 * CF + k] = 0.5f * sa;              // sv.im
            bBase[2 * CF + k] = 0.5f * cB;
            bBase[3 * CF + k] = 0.5f * sb;
        }
    }
}

// ---------------------------------------------------------------------------
extern "C" void kernel_launch(void* const* d_in, const int* in_sizes, int n_in,
                              void* d_out, int out_size) {
    const float* x     = (const float*)d_in[0];
    const float* angle = (const float*)d_in[1];
    const float* mic   = (const float*)d_in[2];
    float* out = (float*)d_out;

    prep_kernel<<<1, 64>>>(angle, mic);

    dim3 grid((TT + 3) / 4, BB * 2);
    stft_kernel<<<grid, 256>>>(x, out);
}